// round 12
// baseline (speedup 1.0000x reference)
#include <cuda_runtime.h>
#include <cstdint>

#define BB 4
#define HH 8
#define SS 2048
#define DD 512
#define DH 64
#define TOPK 10

// Scratch: Q,K transposed [bh][d][s] (d-major for attn GEMM staging);
// V row-major [bh][s][d] (context reads rows).
__device__ float g_Qt[BB*HH*DH*SS];
__device__ float g_Kt[BB*HH*DH*SS];
__device__ float g_V [BB*HH*SS*DH];

__device__ __forceinline__ float neg_inf() { return __int_as_float(0xff800000); }

__device__ __forceinline__ void cpa16(void* s, const void* g) {
    uint32_t sa = (uint32_t)__cvta_generic_to_shared(s);
    asm volatile("cp.async.cg.shared.global [%0], [%1], 16;" :: "r"(sa), "l"(g));
}
__device__ __forceinline__ void cpa_commit() {
    asm volatile("cp.async.commit_group;");
}
__device__ __forceinline__ void cpa_wait0() {
    asm volatile("cp.async.wait_group 0;");
}

// ---------------------------------------------------------------------------
// Kernel 1: Y = x @ W^T + b; Q,K scattered transposed, V row-major.
// Serial ascending-k FMA chain per output (bit-exact, matches reference).
// AT the 3-reg FFMA roofline. Also zero-fills out_attn (2 STG.128 per thread
// per k-tile, hidden in the FMA shadow; DRAM is otherwise idle here).
// ---------------------------------------------------------------------------
__global__ __launch_bounds__(256) void qkv_kernel(
    const float* __restrict__ x,
    const float* __restrict__ Wq, const float* __restrict__ bq,
    const float* __restrict__ Wk, const float* __restrict__ bk,
    const float* __restrict__ Wv, const float* __restrict__ bv,
    float* __restrict__ out_attn)
{
    const int which = blockIdx.z;
    const float* __restrict__ W    = (which == 0) ? Wq : (which == 1) ? Wk : Wv;
    const float* __restrict__ bias = (which == 0) ? bq : (which == 1) ? bk : bv;

    __shared__ float As[16][68];   // [k][m], padded
    __shared__ float Bs[16][68];   // [k][n], padded

    const int tid = threadIdx.x;
    const int tx  = tid & 15;       // 0..15 -> n
    const int ty  = tid >> 4;       // 0..15 -> m
    const int m0  = blockIdx.y * 64;
    const int n0  = blockIdx.x * 64;   // one head per n-tile (DH==64)

    const int lrow = tid >> 2;      // 0..63
    const int lk4  = tid & 3;       // 0..3

    // Zero-fill assignment: grid-stride over float4s of out_attn.
    const int  bid   = blockIdx.x + (blockIdx.y << 3) + (blockIdx.z << 10); // 0..3071
    const uint32_t gtid = tid + (bid << 8);            // 0..786431
    const uint32_t zstride = 3072u * 256u;             // total threads
    const uint32_t ztotal  = (uint32_t)((size_t)BB * HH * SS * SS / 4);  // 33554432
    float4* __restrict__ zdst = (float4*)out_attn;
    const float4 zf4 = make_float4(0.f, 0.f, 0.f, 0.f);

    float c[4][4];
    #pragma unroll
    for (int i = 0; i < 4; ++i)
        #pragma unroll
        for (int j = 0; j < 4; ++j) c[i][j] = 0.f;

    for (int kt = 0; kt < DD / 16; ++kt) {
        float4 av = *(const float4*)&x[(size_t)(m0 + lrow) * DD + kt * 16 + lk4 * 4];
        float4 bv4 = *(const float4*)&W[(size_t)(n0 + lrow) * DD + kt * 16 + lk4 * 4];
        __syncthreads();
        As[lk4 * 4 + 0][lrow] = av.x;
        As[lk4 * 4 + 1][lrow] = av.y;
        As[lk4 * 4 + 2][lrow] = av.z;
        As[lk4 * 4 + 3][lrow] = av.w;
        Bs[lk4 * 4 + 0][lrow] = bv4.x;
        Bs[lk4 * 4 + 1][lrow] = bv4.y;
        Bs[lk4 * 4 + 2][lrow] = bv4.z;
        Bs[lk4 * 4 + 3][lrow] = bv4.w;
        __syncthreads();

        // Two zero stores per tile, drained by the write buffer under the FMAs.
        {
            uint32_t i0 = gtid + (uint32_t)(kt * 2 + 0) * zstride;
            uint32_t i1 = gtid + (uint32_t)(kt * 2 + 1) * zstride;
            if (i0 < ztotal) zdst[i0] = zf4;
            if (i1 < ztotal) zdst[i1] = zf4;
        }

        // k ascending; each c[i][j] is one serial FMA chain over all 512 k.
        #pragma unroll
        for (int k = 0; k < 16; ++k) {
            float4 a  = *(const float4*)&As[k][ty * 4];
            float4 b4 = *(const float4*)&Bs[k][tx * 4];
            c[0][0] = fmaf(a.x, b4.x, c[0][0]); c[0][1] = fmaf(a.x, b4.y, c[0][1]);
            c[0][2] = fmaf(a.x, b4.z, c[0][2]); c[0][3] = fmaf(a.x, b4.w, c[0][3]);
            c[1][0] = fmaf(a.y, b4.x, c[1][0]); c[1][1] = fmaf(a.y, b4.y, c[1][1]);
            c[1][2] = fmaf(a.y, b4.z, c[1][2]); c[1][3] = fmaf(a.y, b4.w, c[1][3]);
            c[2][0] = fmaf(a.z, b4.x, c[2][0]); c[2][1] = fmaf(a.z, b4.y, c[2][1]);
            c[2][2] = fmaf(a.z, b4.z, c[2][2]); c[2][3] = fmaf(a.z, b4.w, c[2][3]);
            c[3][0] = fmaf(a.w, b4.x, c[3][0]); c[3][1] = fmaf(a.w, b4.y, c[3][1]);
            c[3][2] = fmaf(a.w, b4.z, c[3][2]); c[3][3] = fmaf(a.w, b4.w, c[3][3]);
        }
    }

    float4 biasv = *(const float4*)&bias[n0 + tx * 4];
    const int head = blockIdx.x;
    #pragma unroll
    for (int i = 0; i < 4; ++i) {
        int m  = m0 + ty * 4 + i;
        int b_ = m >> 11;        // m / 2048
        int s_ = m & 2047;
        float o0 = c[i][0] + biasv.x;
        float o1 = c[i][1] + biasv.y;
        float o2 = c[i][2] + biasv.z;
        float o3 = c[i][3] + biasv.w;
        if (which == 2) {
            float4 o; o.x = o0; o.y = o1; o.z = o2; o.w = o3;
            *(float4*)&g_V[(size_t)(((b_ * HH + head) * SS) + s_) * DH + tx * 4] = o;
        } else {
            float* dst = (which == 0) ? g_Qt : g_Kt;
            size_t base = ((size_t)(b_ * HH + head) * DH + tx * 4) * SS + s_;
            dst[base + 0 * SS] = o0;
            dst[base + 1 * SS] = o1;
            dst[base + 2 * SS] = o2;
            dst[base + 3 * SS] = o3;
        }
    }
}

// ---------------------------------------------------------------------------
// Kernel 2: per (b,h, 32-q-row tile). 256 threads; each a 4q x 4k sub-tile of
// a 32q x 128k score tile. Warp geometry: ty=tid>>5 constant per warp -> the
// q LDS is a single-address broadcast; k LDS spans 512B conflict-free.
// 16 k-tiles (half the barriers of 64-wide). Single Bs, cp.async prefetch
// overlapping the scan (R8 pipeline). Sc stride 132 (33 float4-slots: dump
// and scan both hit 32 distinct banks). d-loop strictly serial ascending per
// accumulator (bit-exact chain). Scan keeps per-thread top-10 (8 thr/row);
// merge 8 lists/row; softmax; scatter attn (rest zeroed by qkv); context.
// ---------------------------------------------------------------------------
__global__ __launch_bounds__(256, 3) void attn_kernel(
    float* __restrict__ out_ctx, float* __restrict__ out_attn)
{
    extern __shared__ float sm[];
    float* As = sm;                   // 64 x 36  [d][q]   (2304 floats)
    float* Bs = sm + 2304;            // 64 x 132 [d][k]   (8448 floats)
    float* Sc = sm + 10752;           // 32 x 132 [q][k]   (4224 floats)
    // Post-loop overlays (dead after the k-loop):
    float* cv  = Bs;                  // 256*10 floats
    int*   ci  = (int*)(Bs + 2560);   // 256*10 ints
    float* pb  = As;                  // 32*10 floats
    int*   tix = (int*)(As + 320);    // 32*10 ints

    const int qt  = blockIdx.x;       // 0..63 (32 q-rows each)
    const int bh  = blockIdx.y;       // 0..31
    const int tid = threadIdx.x;      // 0..255
    const int ty  = tid >> 5;         // 0..7  -> q rows ty*4..+3 (warp-const)
    const int tx  = tid & 31;         // 0..31 -> k cols tx*4..+3
    const int srow = tid >> 3;        // 0..31 scan row
    const int scg  = tid & 7;         // 0..7  scan col group (16 cols)

    const float* __restrict__ Qt = g_Qt + (size_t)bh * DH * SS;
    const float* __restrict__ Kt = g_Kt + (size_t)bh * DH * SS;
    const float* __restrict__ Vb = g_V  + (size_t)bh * SS * DH;

    // Stage As = Q^T tile (64d x 32q), scaled by 1/8 (exact pow2).
    #pragma unroll
    for (int p = 0; p < 2; ++p) {
        int idx = p * 256 + tid;      // 0..511 float4s
        int d   = idx >> 3;
        int qf4 = idx & 7;
        float4 v = *(const float4*)&Qt[(size_t)d * SS + qt * 32 + qf4 * 4];
        v.x *= 0.125f; v.y *= 0.125f; v.z *= 0.125f; v.w *= 0.125f;
        *(float4*)&As[d * 36 + qf4 * 4] = v;
    }

    // Preload K tile 0 via cp.async (8 float4 per thread; 2048 total).
    #pragma unroll
    for (int p = 0; p < 8; ++p) {
        int idx = p * 256 + tid;      // 0..2047 float4s
        int d   = idx >> 5;
        int kf4 = idx & 31;
        cpa16(&Bs[d * 132 + kf4 * 4], &Kt[(size_t)d * SS + kf4 * 4]);
    }
    cpa_commit();
    cpa_wait0();
    __syncthreads();                   // As + Bs(tile 0) ready

    float tv[TOPK];
    int   ti[TOPK];
    #pragma unroll
    for (int t = 0; t < TOPK; ++t) { tv[t] = neg_inf(); ti[t] = 0x7FFFFFFF; }

    const int NT = SS / 128;           // 16 tiles
    for (int kt = 0; kt < NT; ++kt) {
        // GEMM: 4x4 accumulators, d ascending serial per accumulator.
        float a0[4], a1[4], a2[4], a3[4];
        #pragma unroll
        for (int j = 0; j < 4; ++j) { a0[j]=0.f; a1[j]=0.f; a2[j]=0.f; a3[j]=0.f; }
        #pragma unroll 8
        for (int d = 0; d < 64; ++d) {
            float4 q = *(const float4*)&As[d * 36 + ty * 4];   // warp broadcast
            float4 k = *(const float4*)&Bs[d * 132 + tx * 4];  // 512B span
            a0[0]=fmaf(q.x,k.x,a0[0]); a0[1]=fmaf(q.x,k.y,a0[1]);
            a0[2]=fmaf(q.x,k.z,a0[2]); a0[3]=fmaf(q.x,k.w,a0[3]);
            a1[0]=fmaf(q.y,k.x,a1[0]); a1[1]=fmaf(q.y,k.y,a1[1]);
            a1[2]=fmaf(q.y,k.z,a1[2]); a1[3]=fmaf(q.y,k.w,a1[3]);
            a2[0]=fmaf(q.z,k.x,a2[0]); a2[1]=fmaf(q.z,k.y,a2[1]);
            a2[2]=fmaf(q.z,k.z,a2[2]); a2[3]=fmaf(q.z,k.w,a2[3]);
            a3[0]=fmaf(q.w,k.x,a3[0]); a3[1]=fmaf(q.w,k.y,a3[1]);
            a3[2]=fmaf(q.w,k.z,a3[2]); a3[3]=fmaf(q.w,k.w,a3[3]);
        }
        // Dump scores to smem (bank-verified conflict-free).
        *(float4*)&Sc[(ty*4+0)*132 + tx*4] = make_float4(a0[0],a0[1],a0[2],a0[3]);
        *(float4*)&Sc[(ty*4+1)*132 + tx*4] = make_float4(a1[0],a1[1],a1[2],a1[3]);
        *(float4*)&Sc[(ty*4+2)*132 + tx*4] = make_float4(a2[0],a2[1],a2[2],a2[3]);
        *(float4*)&Sc[(ty*4+3)*132 + tx*4] = make_float4(a3[0],a3[1],a3[2],a3[3]);
        __syncthreads();              // all GEMM reads of Bs done; Sc ready

        // Prefetch next K tile into Bs — overlaps the scan below.
        if (kt + 1 < NT) {
            #pragma unroll
            for (int p = 0; p < 8; ++p) {
                int idx = p * 256 + tid;
                int d   = idx >> 5;
                int kf4 = idx & 31;
                cpa16(&Bs[d * 132 + kf4 * 4],
                      &Kt[(size_t)d * SS + (kt + 1) * 128 + kf4 * 4]);
            }
            cpa_commit();
        }

        // Scan this thread's 16 columns of its row, ascending k, with a
        // max-of-4 fast path (selection semantics identical).
        #pragma unroll
        for (int j4 = 0; j4 < 4; ++j4) {
            float4 s = *(const float4*)&Sc[srow * 132 + scg * 16 + j4 * 4];
            float mx4 = fmaxf(fmaxf(s.x, s.y), fmaxf(s.z, s.w));
            if (mx4 > tv[TOPK - 1]) {
                int k0 = kt * 128 + scg * 16 + j4 * 4;
                float sv[4] = {s.x, s.y, s.z, s.w};
                #pragma unroll
                for (int e = 0; e < 4; ++e) {
                    if (sv[e] > tv[TOPK - 1]) {
                        float vs = sv[e]; int is = k0 + e;
                        #pragma unroll
                        for (int t = 0; t < TOPK; ++t) {
                            if (vs > tv[t]) {
                                float tmpv = tv[t]; tv[t] = vs; vs = tmpv;
                                int tmpi = ti[t]; ti[t] = is; is = tmpi;
                            }
                        }
                    }
                }
            }
        }
        cpa_wait0();
        __syncthreads();              // next Bs tile resident; scans done
    }

    // Candidate lists into overlay (Bs dead after final sync above).
    #pragma unroll
    for (int t = 0; t < TOPK; ++t) {
        cv[tid * TOPK + t] = tv[t];
        ci[tid * TOPK + t] = ti[t];
    }
    __syncthreads();

    // Merge 8 candidate lists per row; ties -> lower index (lax.top_k).
    if (tid < 32) {
        int base = tid * 8 * TOPK;
        for (int s = 0; s < TOPK; ++s) {
            float best = neg_inf(); int bi = 0x7FFFFFFF; int bp = 0;
            for (int p = 0; p < 8 * TOPK; ++p) {
                float v = cv[base + p]; int ii = ci[base + p];
                if (v > best || (v == best && ii < bi)) { best = v; bi = ii; bp = p; }
            }
            cv[base + bp] = neg_inf();
            pb[tid * TOPK + s] = best;
            tix[tid * TOPK + s] = bi;
        }
        float mx = pb[tid * TOPK];
        float pr[TOPK]; float Z = 0.f;
        #pragma unroll
        for (int s = 0; s < TOPK; ++s) {
            float e = expf(pb[tid * TOPK + s] - mx);
            pr[s] = e; Z += e;
        }
        #pragma unroll
        for (int s = 0; s < TOPK; ++s) pb[tid * TOPK + s] = pr[s] / Z;
    }
    __syncthreads();

    const int q = qt * 32 + srow;
    const size_t abase = ((size_t)bh * SS + q) * SS;
    for (int t = scg; t < TOPK; t += 8)
        out_attn[abase + tix[srow * TOPK + t]] = pb[srow * TOPK + t];

    // Context: 8 threads per row, 8 dh-columns each.
    float acc[8];
    #pragma unroll
    for (int j = 0; j < 8; ++j) acc[j] = 0.f;
    #pragma unroll
    for (int t = 0; t < TOPK; ++t) {
        float p = pb[srow * TOPK + t];
        const float* vr = &Vb[(size_t)tix[srow * TOPK + t] * DH + scg * 8];
        float4 v0 = *(const float4*)&vr[0];
        float4 v1 = *(const float4*)&vr[4];
        acc[0] = fmaf(p, v0.x, acc[0]); acc[1] = fmaf(p, v0.y, acc[1]);
        acc[2] = fmaf(p, v0.z, acc[2]); acc[3] = fmaf(p, v0.w, acc[3]);
        acc[4] = fmaf(p, v1.x, acc[4]); acc[5] = fmaf(p, v1.y, acc[5]);
        acc[6] = fmaf(p, v1.z, acc[6]); acc[7] = fmaf(p, v1.w, acc[7]);
    }
    const int b_ = bh >> 3, h_ = bh & 7;
    float* dst = out_ctx + ((size_t)(b_ * SS + q)) * DD + h_ * DH + scg * 8;
    float4 o0, o1;
    o0.x = acc[0]; o0.y = acc[1]; o0.z = acc[2]; o0.w = acc[3];
    o1.x = acc[4]; o1.y = acc[5]; o1.z = acc[6]; o1.w = acc[7];
    *(float4*)&dst[0] = o0;
    *(float4*)&dst[4] = o1;
}

// ---------------------------------------------------------------------------
extern "C" void kernel_launch(void* const* d_in, const int* in_sizes, int n_in,
                              void* d_out, int out_size)
{
    const float* x  = (const float*)d_in[0];
    const float* Wq = (const float*)d_in[1];
    const float* bq = (const float*)d_in[2];
    const float* Wk = (const float*)d_in[3];
    const float* bk = (const float*)d_in[4];
    const float* Wv = (const float*)d_in[5];
    const float* bv = (const float*)d_in[6];

    float* out_ctx  = (float*)d_out;
    float* out_attn = out_ctx + (size_t)BB * SS * DD;

    const int attn_smem = 14976 * 4;   // As + Bs + Sc floats = 59904 B
    cudaFuncSetAttribute(attn_kernel,
                         cudaFuncAttributeMaxDynamicSharedMemorySize, attn_smem);

    // qkv also zero-fills out_attn (grid-stride, hidden in FMA shadow).
    dim3 g1(DD / 64, (BB * SS) / 64, 3);   // (8, 128, 3)
    qkv_kernel<<<g1, 256>>>(x, Wq, bq, Wk, bk, Wv, bv, out_attn);

    dim3 g2(SS / 32, BB * HH);             // (64, 32)
    attn_kernel<<<g2, 256, attn_smem>>>(out_ctx, out_attn);
}

// round 13
// speedup vs baseline: 1.1494x; 1.1494x over previous
#include <cuda_runtime.h>
#include <cstdint>

#define BB 4
#define HH 8
#define SS 2048
#define DD 512
#define DH 64
#define TOPK 10

// Scratch: Q,K transposed [bh][d][s] (d-major for attn GEMM staging);
// V row-major [bh][s][d] (context reads rows).
__device__ float g_Qt[BB*HH*DH*SS];
__device__ float g_Kt[BB*HH*DH*SS];
__device__ float g_V [BB*HH*SS*DH];

__device__ __forceinline__ float neg_inf() { return __int_as_float(0xff800000); }

__device__ __forceinline__ void cpa16(void* s, const void* g) {
    uint32_t sa = (uint32_t)__cvta_generic_to_shared(s);
    asm volatile("cp.async.cg.shared.global [%0], [%1], 16;" :: "r"(sa), "l"(g));
}
__device__ __forceinline__ void cpa_commit() {
    asm volatile("cp.async.commit_group;");
}
__device__ __forceinline__ void cpa_wait0() {
    asm volatile("cp.async.wait_group 0;");
}

// ---------------------------------------------------------------------------
// Kernel 1: Y = x @ W^T + b; Q,K scattered transposed, V row-major.
// Serial ascending-k FMA chain per output (bit-exact, matches reference).
// AT the 3-reg FFMA roofline. Also zero-fills out_attn (2 STG.128 per thread
// per k-tile, hidden in the FMA shadow; DRAM is otherwise idle here).
// ---------------------------------------------------------------------------
__global__ __launch_bounds__(256) void qkv_kernel(
    const float* __restrict__ x,
    const float* __restrict__ Wq, const float* __restrict__ bq,
    const float* __restrict__ Wk, const float* __restrict__ bk,
    const float* __restrict__ Wv, const float* __restrict__ bv,
    float* __restrict__ out_attn)
{
    const int which = blockIdx.z;
    const float* __restrict__ W    = (which == 0) ? Wq : (which == 1) ? Wk : Wv;
    const float* __restrict__ bias = (which == 0) ? bq : (which == 1) ? bk : bv;

    __shared__ float As[16][68];   // [k][m], padded
    __shared__ float Bs[16][68];   // [k][n], padded

    const int tid = threadIdx.x;
    const int tx  = tid & 15;       // 0..15 -> n
    const int ty  = tid >> 4;       // 0..15 -> m
    const int m0  = blockIdx.y * 64;
    const int n0  = blockIdx.x * 64;   // one head per n-tile (DH==64)

    const int lrow = tid >> 2;      // 0..63
    const int lk4  = tid & 3;       // 0..3

    // Zero-fill assignment: grid-stride over float4s of out_attn.
    const int  bid   = blockIdx.x + (blockIdx.y << 3) + (blockIdx.z << 10); // 0..3071
    const uint32_t gtid = tid + (bid << 8);            // 0..786431
    const uint32_t zstride = 3072u * 256u;             // total threads
    const uint32_t ztotal  = (uint32_t)((size_t)BB * HH * SS * SS / 4);  // 33554432
    float4* __restrict__ zdst = (float4*)out_attn;
    const float4 zf4 = make_float4(0.f, 0.f, 0.f, 0.f);

    float c[4][4];
    #pragma unroll
    for (int i = 0; i < 4; ++i)
        #pragma unroll
        for (int j = 0; j < 4; ++j) c[i][j] = 0.f;

    for (int kt = 0; kt < DD / 16; ++kt) {
        float4 av = *(const float4*)&x[(size_t)(m0 + lrow) * DD + kt * 16 + lk4 * 4];
        float4 bv4 = *(const float4*)&W[(size_t)(n0 + lrow) * DD + kt * 16 + lk4 * 4];
        __syncthreads();
        As[lk4 * 4 + 0][lrow] = av.x;
        As[lk4 * 4 + 1][lrow] = av.y;
        As[lk4 * 4 + 2][lrow] = av.z;
        As[lk4 * 4 + 3][lrow] = av.w;
        Bs[lk4 * 4 + 0][lrow] = bv4.x;
        Bs[lk4 * 4 + 1][lrow] = bv4.y;
        Bs[lk4 * 4 + 2][lrow] = bv4.z;
        Bs[lk4 * 4 + 3][lrow] = bv4.w;
        __syncthreads();

        // Two zero stores per tile, drained by the write buffer under the FMAs.
        {
            uint32_t i0 = gtid + (uint32_t)(kt * 2 + 0) * zstride;
            uint32_t i1 = gtid + (uint32_t)(kt * 2 + 1) * zstride;
            if (i0 < ztotal) zdst[i0] = zf4;
            if (i1 < ztotal) zdst[i1] = zf4;
        }

        // k ascending; each c[i][j] is one serial FMA chain over all 512 k.
        #pragma unroll
        for (int k = 0; k < 16; ++k) {
            float4 a  = *(const float4*)&As[k][ty * 4];
            float4 b4 = *(const float4*)&Bs[k][tx * 4];
            c[0][0] = fmaf(a.x, b4.x, c[0][0]); c[0][1] = fmaf(a.x, b4.y, c[0][1]);
            c[0][2] = fmaf(a.x, b4.z, c[0][2]); c[0][3] = fmaf(a.x, b4.w, c[0][3]);
            c[1][0] = fmaf(a.y, b4.x, c[1][0]); c[1][1] = fmaf(a.y, b4.y, c[1][1]);
            c[1][2] = fmaf(a.y, b4.z, c[1][2]); c[1][3] = fmaf(a.y, b4.w, c[1][3]);
            c[2][0] = fmaf(a.z, b4.x, c[2][0]); c[2][1] = fmaf(a.z, b4.y, c[2][1]);
            c[2][2] = fmaf(a.z, b4.z, c[2][2]); c[2][3] = fmaf(a.z, b4.w, c[2][3]);
            c[3][0] = fmaf(a.w, b4.x, c[3][0]); c[3][1] = fmaf(a.w, b4.y, c[3][1]);
            c[3][2] = fmaf(a.w, b4.z, c[3][2]); c[3][3] = fmaf(a.w, b4.w, c[3][3]);
        }
    }

    float4 biasv = *(const float4*)&bias[n0 + tx * 4];
    const int head = blockIdx.x;
    #pragma unroll
    for (int i = 0; i < 4; ++i) {
        int m  = m0 + ty * 4 + i;
        int b_ = m >> 11;        // m / 2048
        int s_ = m & 2047;
        float o0 = c[i][0] + biasv.x;
        float o1 = c[i][1] + biasv.y;
        float o2 = c[i][2] + biasv.z;
        float o3 = c[i][3] + biasv.w;
        if (which == 2) {
            float4 o; o.x = o0; o.y = o1; o.z = o2; o.w = o3;
            *(float4*)&g_V[(size_t)(((b_ * HH + head) * SS) + s_) * DH + tx * 4] = o;
        } else {
            float* dst = (which == 0) ? g_Qt : g_Kt;
            size_t base = ((size_t)(b_ * HH + head) * DH + tx * 4) * SS + s_;
            dst[base + 0 * SS] = o0;
            dst[base + 1 * SS] = o1;
            dst[base + 2 * SS] = o2;
            dst[base + 3 * SS] = o3;
        }
    }
}

// ---------------------------------------------------------------------------
// Kernel 2 (R8/R11 form — confirmed local optimum geometry; only change:
// launch_bounds occupancy 5 -> 6 blocks/SM via 85-reg cap). Per (b,h,
// 32-q-row tile): 128 threads, each a 4q x 4k sub-tile of a 32q x 64k score
// tile; d-loop strictly serial ascending per accumulator (bit-exact chain).
// Single Bs with cp.async prefetch overlapping the scan. Sc stride 68
// (conflict-free). Scan keeps per-thread top-10; merge 4 lists/row; softmax;
// scatter attn (rest zeroed by qkv_kernel); context from V rows.
// ---------------------------------------------------------------------------
__global__ __launch_bounds__(128, 6) void attn_kernel(
    float* __restrict__ out_ctx, float* __restrict__ out_attn)
{
    __shared__ float As[64 * 36];        // Q  [d][q]
    __shared__ float Bs[64 * 68];        // K  [d][k]
    __shared__ float Sc[32 * 68];        // scores [q][k]
    // Post-loop overlays (regions dead after the last GEMM/scan):
    float* cv  = Bs;                     // 128*10 floats
    int*   ci  = (int*)(Bs + 1280);      // 128*10 ints
    float* pb  = As;                     // 32*10 floats
    int*   tix = (int*)(As + 320);       // 32*10 ints

    const int qt  = blockIdx.x;      // 0..63 (32 q-rows each)
    const int bh  = blockIdx.y;      // 0..31
    const int tid = threadIdx.x;     // 0..127
    const int ty  = tid >> 4;        // 0..7  -> q rows ty*4..+3
    const int tx  = tid & 15;        // 0..15 -> k cols tx*4..+3
    const int srow = tid >> 2;       // 0..31 scan row
    const int scg  = tid & 3;        // 0..3  scan col group

    const float* __restrict__ Qt = g_Qt + (size_t)bh * DH * SS;
    const float* __restrict__ Kt = g_Kt + (size_t)bh * DH * SS;
    const float* __restrict__ Vb = g_V  + (size_t)bh * SS * DH;

    // Stage As = Q^T tile (64d x 32q), scaled by 1/8 (exact pow2).
    #pragma unroll
    for (int p = 0; p < 4; ++p) {
        int idx = p * 128 + tid;     // 0..511 float4s
        int d   = idx >> 3;
        int qf4 = idx & 7;
        float4 v = *(const float4*)&Qt[(size_t)d * SS + qt * 32 + qf4 * 4];
        v.x *= 0.125f; v.y *= 0.125f; v.z *= 0.125f; v.w *= 0.125f;
        *(float4*)&As[d * 36 + qf4 * 4] = v;
    }

    // Preload K tile 0 via cp.async (8 float4 per thread).
    #pragma unroll
    for (int p = 0; p < 8; ++p) {
        int idx = p * 128 + tid;     // 0..1023 float4s
        int d   = idx >> 4;
        int kf4 = idx & 15;
        cpa16(&Bs[d * 68 + kf4 * 4], &Kt[(size_t)d * SS + kf4 * 4]);
    }
    cpa_commit();
    cpa_wait0();
    __syncthreads();                  // As + Bs(tile 0) ready

    float tv[TOPK];
    int   ti[TOPK];
    #pragma unroll
    for (int t = 0; t < TOPK; ++t) { tv[t] = neg_inf(); ti[t] = 0x7FFFFFFF; }

    for (int kt = 0; kt < SS / 64; ++kt) {
        // GEMM: 4x4 accumulators, d ascending serial per accumulator.
        float a0[4], a1[4], a2[4], a3[4];
        #pragma unroll
        for (int j = 0; j < 4; ++j) { a0[j]=0.f; a1[j]=0.f; a2[j]=0.f; a3[j]=0.f; }
        #pragma unroll 8
        for (int d = 0; d < 64; ++d) {
            float4 q = *(const float4*)&As[d * 36 + ty * 4];
            float4 k = *(const float4*)&Bs[d * 68 + tx * 4];
            a0[0]=fmaf(q.x,k.x,a0[0]); a0[1]=fmaf(q.x,k.y,a0[1]);
            a0[2]=fmaf(q.x,k.z,a0[2]); a0[3]=fmaf(q.x,k.w,a0[3]);
            a1[0]=fmaf(q.y,k.x,a1[0]); a1[1]=fmaf(q.y,k.y,a1[1]);
            a1[2]=fmaf(q.y,k.z,a1[2]); a1[3]=fmaf(q.y,k.w,a1[3]);
            a2[0]=fmaf(q.z,k.x,a2[0]); a2[1]=fmaf(q.z,k.y,a2[1]);
            a2[2]=fmaf(q.z,k.z,a2[2]); a2[3]=fmaf(q.z,k.w,a2[3]);
            a3[0]=fmaf(q.w,k.x,a3[0]); a3[1]=fmaf(q.w,k.y,a3[1]);
            a3[2]=fmaf(q.w,k.z,a3[2]); a3[3]=fmaf(q.w,k.w,a3[3]);
        }
        // Dump scores to smem.
        *(float4*)&Sc[(ty*4+0)*68 + tx*4] = make_float4(a0[0],a0[1],a0[2],a0[3]);
        *(float4*)&Sc[(ty*4+1)*68 + tx*4] = make_float4(a1[0],a1[1],a1[2],a1[3]);
        *(float4*)&Sc[(ty*4+2)*68 + tx*4] = make_float4(a2[0],a2[1],a2[2],a2[3]);
        *(float4*)&Sc[(ty*4+3)*68 + tx*4] = make_float4(a3[0],a3[1],a3[2],a3[3]);
        __syncthreads();             // all GEMM reads of Bs done; Sc ready

        // Prefetch next K tile into Bs — overlaps the scan below.
        if (kt + 1 < SS / 64) {
            #pragma unroll
            for (int p = 0; p < 8; ++p) {
                int idx = p * 128 + tid;
                int d   = idx >> 4;
                int kf4 = idx & 15;
                cpa16(&Bs[d * 68 + kf4 * 4],
                      &Kt[(size_t)d * SS + (kt + 1) * 64 + kf4 * 4]);
            }
            cpa_commit();
        }

        // Scan this thread's 16 columns of its row, ascending k, with a
        // max-of-4 fast path (selection semantics identical).
        #pragma unroll
        for (int j4 = 0; j4 < 4; ++j4) {
            float4 s = *(const float4*)&Sc[srow * 68 + scg * 16 + j4 * 4];
            float mx4 = fmaxf(fmaxf(s.x, s.y), fmaxf(s.z, s.w));
            if (mx4 > tv[TOPK - 1]) {
                int k0 = kt * 64 + scg * 16 + j4 * 4;
                float sv[4] = {s.x, s.y, s.z, s.w};
                #pragma unroll
                for (int e = 0; e < 4; ++e) {
                    if (sv[e] > tv[TOPK - 1]) {
                        float vs = sv[e]; int is = k0 + e;
                        #pragma unroll
                        for (int t = 0; t < TOPK; ++t) {
                            if (vs > tv[t]) {
                                float tmpv = tv[t]; tv[t] = vs; vs = tmpv;
                                int tmpi = ti[t]; ti[t] = is; is = tmpi;
                            }
                        }
                    }
                }
            }
        }
        cpa_wait0();
        __syncthreads();             // next Bs tile resident; scans done
    }

    // Candidate lists into overlay (Bs dead after final sync above).
    #pragma unroll
    for (int t = 0; t < TOPK; ++t) {
        cv[tid * TOPK + t] = tv[t];
        ci[tid * TOPK + t] = ti[t];
    }
    __syncthreads();

    // Merge 4 candidate lists per row; ties -> lower index (lax.top_k).
    if (tid < 32) {
        int base = tid * 4 * TOPK;
        for (int s = 0; s < TOPK; ++s) {
            float best = neg_inf(); int bi = 0x7FFFFFFF; int bp = 0;
            for (int p = 0; p < 4 * TOPK; ++p) {
                float v = cv[base + p]; int ii = ci[base + p];
                if (v > best || (v == best && ii < bi)) { best = v; bi = ii; bp = p; }
            }
            cv[base + bp] = neg_inf();
            pb[tid * TOPK + s] = best;
            tix[tid * TOPK + s] = bi;
        }
        float mx = pb[tid * TOPK];
        float pr[TOPK]; float Z = 0.f;
        #pragma unroll
        for (int s = 0; s < TOPK; ++s) {
            float e = expf(pb[tid * TOPK + s] - mx);
            pr[s] = e; Z += e;
        }
        #pragma unroll
        for (int s = 0; s < TOPK; ++s) pb[tid * TOPK + s] = pr[s] / Z;
    }
    __syncthreads();

    const int q = qt * 32 + srow;
    const size_t abase = ((size_t)bh * SS + q) * SS;
    for (int t = scg; t < TOPK; t += 4)
        out_attn[abase + tix[srow * TOPK + t]] = pb[srow * TOPK + t];

    // Context: 4 threads per row, 16 dh-columns each.
    float acc[16];
    #pragma unroll
    for (int j = 0; j < 16; ++j) acc[j] = 0.f;
    #pragma unroll
    for (int t = 0; t < TOPK; ++t) {
        float p = pb[srow * TOPK + t];
        const float* vr = &Vb[(size_t)tix[srow * TOPK + t] * DH + scg * 16];
        #pragma unroll
        for (int j4 = 0; j4 < 4; ++j4) {
            float4 v = *(const float4*)&vr[j4 * 4];
            acc[j4*4+0] = fmaf(p, v.x, acc[j4*4+0]);
            acc[j4*4+1] = fmaf(p, v.y, acc[j4*4+1]);
            acc[j4*4+2] = fmaf(p, v.z, acc[j4*4+2]);
            acc[j4*4+3] = fmaf(p, v.w, acc[j4*4+3]);
        }
    }
    const int b_ = bh >> 3, h_ = bh & 7;
    float* dst = out_ctx + ((size_t)(b_ * SS + q)) * DD + h_ * DH + scg * 16;
    #pragma unroll
    for (int j4 = 0; j4 < 4; ++j4) {
        float4 o;
        o.x = acc[j4*4+0]; o.y = acc[j4*4+1];
        o.z = acc[j4*4+2]; o.w = acc[j4*4+3];
        *(float4*)&dst[j4 * 4] = o;
    }
}

// ---------------------------------------------------------------------------
extern "C" void kernel_launch(void* const* d_in, const int* in_sizes, int n_in,
                              void* d_out, int out_size)
{
    const float* x  = (const float*)d_in[0];
    const float* Wq = (const float*)d_in[1];
    const float* bq = (const float*)d_in[2];
    const float* Wk = (const float*)d_in[3];
    const float* bk = (const float*)d_in[4];
    const float* Wv = (const float*)d_in[5];
    const float* bv = (const float*)d_in[6];

    float* out_ctx  = (float*)d_out;
    float* out_attn = out_ctx + (size_t)BB * SS * DD;

    // qkv also zero-fills out_attn (grid-stride, hidden in FMA shadow).
    dim3 g1(DD / 64, (BB * SS) / 64, 3);   // (8, 128, 3)
    qkv_kernel<<<g1, 256>>>(x, Wq, bq, Wk, bk, Wv, bv, out_attn);

    dim3 g2(SS / 32, BB * HH);             // (64, 32)
    attn_kernel<<<g2, 128>>>(out_ctx, out_attn);
}

// round 14
// speedup vs baseline: 1.2132x; 1.0556x over previous
#include <cuda_runtime.h>
#include <cstdint>

#define BB 4
#define HH 8
#define SS 2048
#define DD 512
#define DH 64
#define TOPK 10

// Scratch: Q,K transposed [bh][d][s] (d-major, for attn staging);
// K,V row-major [bh][s][d] (rescore / context read rows).
__device__ float g_Qt[BB*HH*DH*SS];
__device__ float g_Kt[BB*HH*DH*SS];
__device__ float g_K [BB*HH*SS*DH];
__device__ float g_V [BB*HH*SS*DH];

__device__ __forceinline__ float neg_inf() { return __int_as_float(0xff800000); }

__device__ __forceinline__ void cpa16(void* s, const void* g) {
    uint32_t sa = (uint32_t)__cvta_generic_to_shared(s);
    asm volatile("cp.async.cg.shared.global [%0], [%1], 16;" :: "r"(sa), "l"(g));
}
__device__ __forceinline__ void cpa_commit() {
    asm volatile("cp.async.commit_group;");
}
__device__ __forceinline__ void cpa_wait0() {
    asm volatile("cp.async.wait_group 0;");
}

// ---------------------------------------------------------------------------
// Kernel 1: Y = x @ W^T + b; Q,K transposed scatter, K also row-major,
// V row-major. Serial ascending-k FMA chain per output (bit-exact).
// Also zero-fills out_attn (hidden in the FMA shadow).
// ---------------------------------------------------------------------------
__global__ __launch_bounds__(256) void qkv_kernel(
    const float* __restrict__ x,
    const float* __restrict__ Wq, const float* __restrict__ bq,
    const float* __restrict__ Wk, const float* __restrict__ bk,
    const float* __restrict__ Wv, const float* __restrict__ bv,
    float* __restrict__ out_attn)
{
    const int which = blockIdx.z;
    const float* __restrict__ W    = (which == 0) ? Wq : (which == 1) ? Wk : Wv;
    const float* __restrict__ bias = (which == 0) ? bq : (which == 1) ? bk : bv;

    __shared__ float As[16][68];   // [k][m], padded
    __shared__ float Bs[16][68];   // [k][n], padded

    const int tid = threadIdx.x;
    const int tx  = tid & 15;       // 0..15 -> n
    const int ty  = tid >> 4;       // 0..15 -> m
    const int m0  = blockIdx.y * 64;
    const int n0  = blockIdx.x * 64;   // one head per n-tile (DH==64)

    const int lrow = tid >> 2;      // 0..63
    const int lk4  = tid & 3;       // 0..3

    // Zero-fill assignment: grid-stride over float4s of out_attn.
    const int  bid   = blockIdx.x + (blockIdx.y << 3) + (blockIdx.z << 10); // 0..3071
    const uint32_t gtid = tid + (bid << 8);            // 0..786431
    const uint32_t zstride = 3072u * 256u;             // total threads
    const uint32_t ztotal  = (uint32_t)((size_t)BB * HH * SS * SS / 4);  // 33554432
    float4* __restrict__ zdst = (float4*)out_attn;
    const float4 zf4 = make_float4(0.f, 0.f, 0.f, 0.f);

    float c[4][4];
    #pragma unroll
    for (int i = 0; i < 4; ++i)
        #pragma unroll
        for (int j = 0; j < 4; ++j) c[i][j] = 0.f;

    for (int kt = 0; kt < DD / 16; ++kt) {
        float4 av = *(const float4*)&x[(size_t)(m0 + lrow) * DD + kt * 16 + lk4 * 4];
        float4 bv4 = *(const float4*)&W[(size_t)(n0 + lrow) * DD + kt * 16 + lk4 * 4];
        __syncthreads();
        As[lk4 * 4 + 0][lrow] = av.x;
        As[lk4 * 4 + 1][lrow] = av.y;
        As[lk4 * 4 + 2][lrow] = av.z;
        As[lk4 * 4 + 3][lrow] = av.w;
        Bs[lk4 * 4 + 0][lrow] = bv4.x;
        Bs[lk4 * 4 + 1][lrow] = bv4.y;
        Bs[lk4 * 4 + 2][lrow] = bv4.z;
        Bs[lk4 * 4 + 3][lrow] = bv4.w;
        __syncthreads();

        // Two zero stores per tile, drained by the write buffer under the FMAs.
        {
            uint32_t i0 = gtid + (uint32_t)(kt * 2 + 0) * zstride;
            uint32_t i1 = gtid + (uint32_t)(kt * 2 + 1) * zstride;
            if (i0 < ztotal) zdst[i0] = zf4;
            if (i1 < ztotal) zdst[i1] = zf4;
        }

        // k ascending; each c[i][j] is one serial FMA chain over all 512 k.
        #pragma unroll
        for (int k = 0; k < 16; ++k) {
            float4 a  = *(const float4*)&As[k][ty * 4];
            float4 b4 = *(const float4*)&Bs[k][tx * 4];
            c[0][0] = fmaf(a.x, b4.x, c[0][0]); c[0][1] = fmaf(a.x, b4.y, c[0][1]);
            c[0][2] = fmaf(a.x, b4.z, c[0][2]); c[0][3] = fmaf(a.x, b4.w, c[0][3]);
            c[1][0] = fmaf(a.y, b4.x, c[1][0]); c[1][1] = fmaf(a.y, b4.y, c[1][1]);
            c[1][2] = fmaf(a.y, b4.z, c[1][2]); c[1][3] = fmaf(a.y, b4.w, c[1][3]);
            c[2][0] = fmaf(a.z, b4.x, c[2][0]); c[2][1] = fmaf(a.z, b4.y, c[2][1]);
            c[2][2] = fmaf(a.z, b4.z, c[2][2]); c[2][3] = fmaf(a.z, b4.w, c[2][3]);
            c[3][0] = fmaf(a.w, b4.x, c[3][0]); c[3][1] = fmaf(a.w, b4.y, c[3][1]);
            c[3][2] = fmaf(a.w, b4.z, c[3][2]); c[3][3] = fmaf(a.w, b4.w, c[3][3]);
        }
    }

    float4 biasv = *(const float4*)&bias[n0 + tx * 4];
    const int head = blockIdx.x;
    #pragma unroll
    for (int i = 0; i < 4; ++i) {
        int m  = m0 + ty * 4 + i;
        int b_ = m >> 11;        // m / 2048
        int s_ = m & 2047;
        float o0 = c[i][0] + biasv.x;
        float o1 = c[i][1] + biasv.y;
        float o2 = c[i][2] + biasv.z;
        float o3 = c[i][3] + biasv.w;
        if (which == 2) {
            float4 o; o.x = o0; o.y = o1; o.z = o2; o.w = o3;
            *(float4*)&g_V[(size_t)(((b_ * HH + head) * SS) + s_) * DH + tx * 4] = o;
        } else {
            float* dst = (which == 0) ? g_Qt : g_Kt;
            size_t base = ((size_t)(b_ * HH + head) * DH + tx * 4) * SS + s_;
            dst[base + 0 * SS] = o0;
            dst[base + 1 * SS] = o1;
            dst[base + 2 * SS] = o2;
            dst[base + 3 * SS] = o3;
            if (which == 1) {   // K also row-major for exact rescore
                float4 o; o.x = o0; o.y = o1; o.z = o2; o.w = o3;
                *(float4*)&g_K[(size_t)(((b_ * HH + head) * SS) + s_) * DH + tx * 4] = o;
            }
        }
    }
}

// ---------------------------------------------------------------------------
// Kernel 2: tf32 tensor-core PREFILTER + exact rescore.
// Per (b,h, 32-q-row tile): 128 threads (4 warps). Approx scores for a
// 32q x 64k tile via mma.m16n8k8.tf32 (warp patch 16q x 32k; 8 k-chunks x
// 4 n-patches). Scan approx scores -> per-thread top-10 INDICES. Then
// rescore all 40 candidates/row with the EXACT serial ascending-d FMA chain
// (As operands identical to the old exact GEMM; K row from g_K), merge
// exact top-10 (lower-index ties), softmax, scatter, context.
// Output bit-identical to the exact kernel given candidate containment.
// ---------------------------------------------------------------------------
__global__ __launch_bounds__(128, 6) void attn_kernel(
    float* __restrict__ out_ctx, float* __restrict__ out_attn)
{
    __shared__ float As[64 * 36];        // Q·0.125  [d][q] (exact fp32)
    __shared__ float Bs[64 * 68];        // K        [d][k]
    __shared__ float Sc[32 * 68];        // approx scores [q][k]
    // Post-loop overlays (regions dead after the last GEMM/scan):
    float* cv  = Bs;                     // 128*10 floats (exact rescored)
    int*   ci  = (int*)(Bs + 1280);      // 128*10 ints   (candidate indices)
    float* pb  = As;                     // 32*10 floats
    int*   tix = (int*)(As + 320);       // 32*10 ints

    const int qt  = blockIdx.x;      // 0..63 (32 q-rows each)
    const int bh  = blockIdx.y;      // 0..31
    const int tid = threadIdx.x;     // 0..127
    // mma geometry
    const int lane = tid & 31;
    const int g    = lane >> 2;      // groupID 0..7
    const int tig  = lane & 3;       // thread-in-group 0..3
    const int qb   = (tid >> 6) * 16;        // warp q base: 0 or 16
    const int kb   = ((tid >> 5) & 1) * 32;  // warp k base: 0 or 32
    // scan geometry
    const int srow = tid >> 2;       // 0..31 scan row
    const int scg  = tid & 3;        // 0..3  scan col group

    const float* __restrict__ Qt = g_Qt + (size_t)bh * DH * SS;
    const float* __restrict__ Kt = g_Kt + (size_t)bh * DH * SS;
    const float* __restrict__ Kr = g_K  + (size_t)bh * SS * DH;
    const float* __restrict__ Vb = g_V  + (size_t)bh * SS * DH;

    // Stage As = Q^T tile (64d x 32q), scaled by 1/8 (exact pow2).
    #pragma unroll
    for (int p = 0; p < 4; ++p) {
        int idx = p * 128 + tid;     // 0..511 float4s
        int d   = idx >> 3;
        int qf4 = idx & 7;
        float4 v = *(const float4*)&Qt[(size_t)d * SS + qt * 32 + qf4 * 4];
        v.x *= 0.125f; v.y *= 0.125f; v.z *= 0.125f; v.w *= 0.125f;
        *(float4*)&As[d * 36 + qf4 * 4] = v;
    }

    // Preload K tile 0 via cp.async (8 float4 per thread).
    #pragma unroll
    for (int p = 0; p < 8; ++p) {
        int idx = p * 128 + tid;     // 0..1023 float4s
        int d   = idx >> 4;
        int kf4 = idx & 15;
        cpa16(&Bs[d * 68 + kf4 * 4], &Kt[(size_t)d * SS + kf4 * 4]);
    }
    cpa_commit();
    cpa_wait0();
    __syncthreads();                  // As + Bs(tile 0) ready

    float tv[TOPK];
    int   ti[TOPK];
    #pragma unroll
    for (int t = 0; t < TOPK; ++t) { tv[t] = neg_inf(); ti[t] = 0x7FFFFFFF; }

    for (int kt = 0; kt < SS / 64; ++kt) {
        // Approx GEMM: 4 n-patches of m16n8, accumulated over 8 k-chunks.
        float c[4][4];
        #pragma unroll
        for (int p = 0; p < 4; ++p)
            #pragma unroll
            for (int j = 0; j < 4; ++j) c[p][j] = 0.f;

        #pragma unroll
        for (int kc = 0; kc < 8; ++kc) {
            const int d0 = kc * 8;
            float a0 = As[(d0 + tig)     * 36 + qb + g];
            float a1 = As[(d0 + tig)     * 36 + qb + g + 8];
            float a2 = As[(d0 + tig + 4) * 36 + qb + g];
            float a3 = As[(d0 + tig + 4) * 36 + qb + g + 8];
            #pragma unroll
            for (int p = 0; p < 4; ++p) {
                const int nb = kb + p * 8;
                float b0 = Bs[(d0 + tig)     * 68 + nb + g];
                float b1 = Bs[(d0 + tig + 4) * 68 + nb + g];
                asm volatile(
                    "mma.sync.aligned.m16n8k8.row.col.f32.tf32.tf32.f32 "
                    "{%0,%1,%2,%3}, {%4,%5,%6,%7}, {%8,%9}, {%0,%1,%2,%3};\n"
                    : "+f"(c[p][0]), "+f"(c[p][1]), "+f"(c[p][2]), "+f"(c[p][3])
                    : "r"(__float_as_uint(a0)), "r"(__float_as_uint(a1)),
                      "r"(__float_as_uint(a2)), "r"(__float_as_uint(a3)),
                      "r"(__float_as_uint(b0)), "r"(__float_as_uint(b1)));
            }
        }
        // Dump approx scores (C frag: c0/c1 at cols 2*tig,+1; c2/c3 at q+8).
        #pragma unroll
        for (int p = 0; p < 4; ++p) {
            const int col = kb + p * 8 + 2 * tig;
            *(float2*)&Sc[(qb + g)     * 68 + col] = make_float2(c[p][0], c[p][1]);
            *(float2*)&Sc[(qb + g + 8) * 68 + col] = make_float2(c[p][2], c[p][3]);
        }
        __syncthreads();             // Sc ready; all reads of Bs done

        // Prefetch next K tile into Bs — overlaps the scan below.
        if (kt + 1 < SS / 64) {
            #pragma unroll
            for (int p = 0; p < 8; ++p) {
                int idx = p * 128 + tid;
                int d   = idx >> 4;
                int kf4 = idx & 15;
                cpa16(&Bs[d * 68 + kf4 * 4],
                      &Kt[(size_t)d * SS + (kt + 1) * 64 + kf4 * 4]);
            }
            cpa_commit();
        }

        // Scan (approx values): per-thread top-10 with max-of-4 fast path.
        #pragma unroll
        for (int j4 = 0; j4 < 4; ++j4) {
            float4 s = *(const float4*)&Sc[srow * 68 + scg * 16 + j4 * 4];
            float mx4 = fmaxf(fmaxf(s.x, s.y), fmaxf(s.z, s.w));
            if (mx4 > tv[TOPK - 1]) {
                int k0 = kt * 64 + scg * 16 + j4 * 4;
                float sv[4] = {s.x, s.y, s.z, s.w};
                #pragma unroll
                for (int e = 0; e < 4; ++e) {
                    if (sv[e] > tv[TOPK - 1]) {
                        float vs = sv[e]; int is = k0 + e;
                        #pragma unroll
                        for (int t = 0; t < TOPK; ++t) {
                            if (vs > tv[t]) {
                                float tmpv = tv[t]; tv[t] = vs; vs = tmpv;
                                int tmpi = ti[t]; ti[t] = is; is = tmpi;
                            }
                        }
                    }
                }
            }
        }
        cpa_wait0();
        __syncthreads();             // next Bs tile resident; scans done
    }

    // Candidate INDICES into overlay (Bs dead after final sync above).
    #pragma unroll
    for (int t = 0; t < TOPK; ++t)
        ci[tid * TOPK + t] = ti[t];
    __syncthreads();

    // EXACT rescore of this thread's 10 candidates: serial ascending-d FMA
    // chain with the same As operands as the exact GEMM; K row from g_K.
    {
        const int r = tid >> 2;       // this thread's q row
        #pragma unroll
        for (int t = 0; t < TOPK; ++t) {
            int kidx = ci[tid * TOPK + t];
            const float4* krow = (const float4*)(Kr + (size_t)kidx * DH);
            float acc = 0.f;
            #pragma unroll
            for (int j = 0; j < 16; ++j) {
                float4 kv = krow[j];
                acc = fmaf(As[(j * 4 + 0) * 36 + r], kv.x, acc);
                acc = fmaf(As[(j * 4 + 1) * 36 + r], kv.y, acc);
                acc = fmaf(As[(j * 4 + 2) * 36 + r], kv.z, acc);
                acc = fmaf(As[(j * 4 + 3) * 36 + r], kv.w, acc);
            }
            cv[tid * TOPK + t] = acc;
        }
    }
    __syncthreads();

    // Merge 4 exact candidate lists per row; ties -> lower index (lax.top_k).
    if (tid < 32) {
        int base = tid * 4 * TOPK;
        for (int s = 0; s < TOPK; ++s) {
            float best = neg_inf(); int bi = 0x7FFFFFFF; int bp = 0;
            for (int p = 0; p < 4 * TOPK; ++p) {
                float v = cv[base + p]; int ii = ci[base + p];
                if (v > best || (v == best && ii < bi)) { best = v; bi = ii; bp = p; }
            }
            cv[base + bp] = neg_inf();
            pb[tid * TOPK + s] = best;
            tix[tid * TOPK + s] = bi;
        }
        float mx = pb[tid * TOPK];
        float pr[TOPK]; float Z = 0.f;
        #pragma unroll
        for (int s = 0; s < TOPK; ++s) {
            float e = expf(pb[tid * TOPK + s] - mx);
            pr[s] = e; Z += e;
        }
        #pragma unroll
        for (int s = 0; s < TOPK; ++s) pb[tid * TOPK + s] = pr[s] / Z;
    }
    __syncthreads();

    const int q = qt * 32 + srow;
    const size_t abase = ((size_t)bh * SS + q) * SS;
    for (int t = scg; t < TOPK; t += 4)
        out_attn[abase + tix[srow * TOPK + t]] = pb[srow * TOPK + t];

    // Context: 4 threads per row, 16 dh-columns each.
    float acc[16];
    #pragma unroll
    for (int j = 0; j < 16; ++j) acc[j] = 0.f;
    #pragma unroll
    for (int t = 0; t < TOPK; ++t) {
        float p = pb[srow * TOPK + t];
        const float* vr = &Vb[(size_t)tix[srow * TOPK + t] * DH + scg * 16];
        #pragma unroll
        for (int j4 = 0; j4 < 4; ++j4) {
            float4 v = *(const float4*)&vr[j4 * 4];
            acc[j4*4+0] = fmaf(p, v.x, acc[j4*4+0]);
            acc[j4*4+1] = fmaf(p, v.y, acc[j4*4+1]);
            acc[j4*4+2] = fmaf(p, v.z, acc[j4*4+2]);
            acc[j4*4+3] = fmaf(p, v.w, acc[j4*4+3]);
        }
    }
    const int b_ = bh >> 3, h_ = bh & 7;
    float* dst = out_ctx + ((size_t)(b_ * SS + q)) * DD + h_ * DH + scg * 16;
    #pragma unroll
    for (int j4 = 0; j4 < 4; ++j4) {
        float4 o;
        o.x = acc[j4*4+0]; o.y = acc[j4*4+1];
        o.z = acc[j4*4+2]; o.w = acc[j4*4+3];
        *(float4*)&dst[j4 * 4] = o;
    }
}

// ---------------------------------------------------------------------------
extern "C" void kernel_launch(void* const* d_in, const int* in_sizes, int n_in,
                              void* d_out, int out_size)
{
    const float* x  = (const float*)d_in[0];
    const float* Wq = (const float*)d_in[1];
    const float* bq = (const float*)d_in[2];
    const float* Wk = (const float*)d_in[3];
    const float* bk = (const float*)d_in[4];
    const float* Wv = (const float*)d_in[5];
    const float* bv = (const float*)d_in[6];

    float* out_ctx  = (float*)d_out;
    float* out_attn = out_ctx + (size_t)BB * SS * DD;

    // qkv also zero-fills out_attn (grid-stride, hidden in FMA shadow).
    dim3 g1(DD / 64, (BB * SS) / 64, 3);   // (8, 128, 3)
    qkv_kernel<<<g1, 256>>>(x, Wq, bq, Wk, bk, Wv, bv, out_attn);

    dim3 g2(SS / 32, BB * HH);             // (64, 32)
    attn_kernel<<<g2, 128>>>(out_ctx, out_attn);
}

// round 15
// speedup vs baseline: 1.2279x; 1.0121x over previous
#include <cuda_runtime.h>
#include <cstdint>

#define BB 4
#define HH 8
#define SS 2048
#define DD 512
#define DH 64
#define TOPK 10

// Scratch: Q,K transposed [bh][d][s] (d-major, for attn staging);
// K,V row-major [bh][s][d] (rescore / context read rows).
__device__ float g_Qt[BB*HH*DH*SS];
__device__ float g_Kt[BB*HH*DH*SS];
__device__ float g_K [BB*HH*SS*DH];
__device__ float g_V [BB*HH*SS*DH];

__device__ __forceinline__ float neg_inf() { return __int_as_float(0xff800000); }

__device__ __forceinline__ void cpa16(void* s, const void* g) {
    uint32_t sa = (uint32_t)__cvta_generic_to_shared(s);
    asm volatile("cp.async.cg.shared.global [%0], [%1], 16;" :: "r"(sa), "l"(g));
}
__device__ __forceinline__ void cpa_commit() {
    asm volatile("cp.async.commit_group;");
}
__device__ __forceinline__ void cpa_wait0() {
    asm volatile("cp.async.wait_group 0;");
}

// ---------------------------------------------------------------------------
// Kernel 1: Y = x @ W^T + b; Q,K transposed scatter, K also row-major,
// V row-major. Serial ascending-k FMA chain per output (bit-exact).
// Also zero-fills out_attn (hidden in the FMA shadow).
// ---------------------------------------------------------------------------
__global__ __launch_bounds__(256) void qkv_kernel(
    const float* __restrict__ x,
    const float* __restrict__ Wq, const float* __restrict__ bq,
    const float* __restrict__ Wk, const float* __restrict__ bk,
    const float* __restrict__ Wv, const float* __restrict__ bv,
    float* __restrict__ out_attn)
{
    const int which = blockIdx.z;
    const float* __restrict__ W    = (which == 0) ? Wq : (which == 1) ? Wk : Wv;
    const float* __restrict__ bias = (which == 0) ? bq : (which == 1) ? bk : bv;

    __shared__ float As[16][68];   // [k][m], padded
    __shared__ float Bs[16][68];   // [k][n], padded

    const int tid = threadIdx.x;
    const int tx  = tid & 15;       // 0..15 -> n
    const int ty  = tid >> 4;       // 0..15 -> m
    const int m0  = blockIdx.y * 64;
    const int n0  = blockIdx.x * 64;   // one head per n-tile (DH==64)

    const int lrow = tid >> 2;      // 0..63
    const int lk4  = tid & 3;       // 0..3

    // Zero-fill assignment: grid-stride over float4s of out_attn.
    const int  bid   = blockIdx.x + (blockIdx.y << 3) + (blockIdx.z << 10); // 0..3071
    const uint32_t gtid = tid + (bid << 8);            // 0..786431
    const uint32_t zstride = 3072u * 256u;             // total threads
    const uint32_t ztotal  = (uint32_t)((size_t)BB * HH * SS * SS / 4);  // 33554432
    float4* __restrict__ zdst = (float4*)out_attn;
    const float4 zf4 = make_float4(0.f, 0.f, 0.f, 0.f);

    float c[4][4];
    #pragma unroll
    for (int i = 0; i < 4; ++i)
        #pragma unroll
        for (int j = 0; j < 4; ++j) c[i][j] = 0.f;

    for (int kt = 0; kt < DD / 16; ++kt) {
        float4 av = *(const float4*)&x[(size_t)(m0 + lrow) * DD + kt * 16 + lk4 * 4];
        float4 bv4 = *(const float4*)&W[(size_t)(n0 + lrow) * DD + kt * 16 + lk4 * 4];
        __syncthreads();
        As[lk4 * 4 + 0][lrow] = av.x;
        As[lk4 * 4 + 1][lrow] = av.y;
        As[lk4 * 4 + 2][lrow] = av.z;
        As[lk4 * 4 + 3][lrow] = av.w;
        Bs[lk4 * 4 + 0][lrow] = bv4.x;
        Bs[lk4 * 4 + 1][lrow] = bv4.y;
        Bs[lk4 * 4 + 2][lrow] = bv4.z;
        Bs[lk4 * 4 + 3][lrow] = bv4.w;
        __syncthreads();

        // Two zero stores per tile, drained by the write buffer under the FMAs.
        {
            uint32_t i0 = gtid + (uint32_t)(kt * 2 + 0) * zstride;
            uint32_t i1 = gtid + (uint32_t)(kt * 2 + 1) * zstride;
            if (i0 < ztotal) zdst[i0] = zf4;
            if (i1 < ztotal) zdst[i1] = zf4;
        }

        // k ascending; each c[i][j] is one serial FMA chain over all 512 k.
        #pragma unroll
        for (int k = 0; k < 16; ++k) {
            float4 a  = *(const float4*)&As[k][ty * 4];
            float4 b4 = *(const float4*)&Bs[k][tx * 4];
            c[0][0] = fmaf(a.x, b4.x, c[0][0]); c[0][1] = fmaf(a.x, b4.y, c[0][1]);
            c[0][2] = fmaf(a.x, b4.z, c[0][2]); c[0][3] = fmaf(a.x, b4.w, c[0][3]);
            c[1][0] = fmaf(a.y, b4.x, c[1][0]); c[1][1] = fmaf(a.y, b4.y, c[1][1]);
            c[1][2] = fmaf(a.y, b4.z, c[1][2]); c[1][3] = fmaf(a.y, b4.w, c[1][3]);
            c[2][0] = fmaf(a.z, b4.x, c[2][0]); c[2][1] = fmaf(a.z, b4.y, c[2][1]);
            c[2][2] = fmaf(a.z, b4.z, c[2][2]); c[2][3] = fmaf(a.z, b4.w, c[2][3]);
            c[3][0] = fmaf(a.w, b4.x, c[3][0]); c[3][1] = fmaf(a.w, b4.y, c[3][1]);
            c[3][2] = fmaf(a.w, b4.z, c[3][2]); c[3][3] = fmaf(a.w, b4.w, c[3][3]);
        }
    }

    float4 biasv = *(const float4*)&bias[n0 + tx * 4];
    const int head = blockIdx.x;
    #pragma unroll
    for (int i = 0; i < 4; ++i) {
        int m  = m0 + ty * 4 + i;
        int b_ = m >> 11;        // m / 2048
        int s_ = m & 2047;
        float o0 = c[i][0] + biasv.x;
        float o1 = c[i][1] + biasv.y;
        float o2 = c[i][2] + biasv.z;
        float o3 = c[i][3] + biasv.w;
        if (which == 2) {
            float4 o; o.x = o0; o.y = o1; o.z = o2; o.w = o3;
            *(float4*)&g_V[(size_t)(((b_ * HH + head) * SS) + s_) * DH + tx * 4] = o;
        } else {
            float* dst = (which == 0) ? g_Qt : g_Kt;
            size_t base = ((size_t)(b_ * HH + head) * DH + tx * 4) * SS + s_;
            dst[base + 0 * SS] = o0;
            dst[base + 1 * SS] = o1;
            dst[base + 2 * SS] = o2;
            dst[base + 3 * SS] = o3;
            if (which == 1) {   // K also row-major for exact rescore
                float4 o; o.x = o0; o.y = o1; o.z = o2; o.w = o3;
                *(float4*)&g_K[(size_t)(((b_ * HH + head) * SS) + s_) * DH + tx * 4] = o;
            }
        }
    }
}

// ---------------------------------------------------------------------------
// Kernel 2: tf32 tensor-core PREFILTER + exact rescore (R14 architecture).
// Change vs R14: A fragments (loop-invariant Q operands) hoisted into 32
// registers before the k-loop — removes 32 of 96 scalar LDS per tile and the
// A-side LDS->MMA dependency. launch_bounds (128,4) for the added registers.
// ---------------------------------------------------------------------------
__global__ __launch_bounds__(128, 4) void attn_kernel(
    float* __restrict__ out_ctx, float* __restrict__ out_attn)
{
    __shared__ float As[64 * 36];        // Q·0.125  [d][q] (exact fp32)
    __shared__ float Bs[64 * 68];        // K        [d][k]
    __shared__ float Sc[32 * 68];        // approx scores [q][k]
    // Post-loop overlays (regions dead after the last GEMM/scan):
    float* cv  = Bs;                     // 128*10 floats (exact rescored)
    int*   ci  = (int*)(Bs + 1280);      // 128*10 ints   (candidate indices)
    float* pb  = As;                     // 32*10 floats
    int*   tix = (int*)(As + 320);       // 32*10 ints

    const int qt  = blockIdx.x;      // 0..63 (32 q-rows each)
    const int bh  = blockIdx.y;      // 0..31
    const int tid = threadIdx.x;     // 0..127
    // mma geometry
    const int lane = tid & 31;
    const int g    = lane >> 2;      // groupID 0..7
    const int tig  = lane & 3;       // thread-in-group 0..3
    const int qb   = (tid >> 6) * 16;        // warp q base: 0 or 16
    const int kb   = ((tid >> 5) & 1) * 32;  // warp k base: 0 or 32
    // scan geometry
    const int srow = tid >> 2;       // 0..31 scan row
    const int scg  = tid & 3;        // 0..3  scan col group

    const float* __restrict__ Qt = g_Qt + (size_t)bh * DH * SS;
    const float* __restrict__ Kt = g_Kt + (size_t)bh * DH * SS;
    const float* __restrict__ Kr = g_K  + (size_t)bh * SS * DH;
    const float* __restrict__ Vb = g_V  + (size_t)bh * SS * DH;

    // Stage As = Q^T tile (64d x 32q), scaled by 1/8 (exact pow2).
    #pragma unroll
    for (int p = 0; p < 4; ++p) {
        int idx = p * 128 + tid;     // 0..511 float4s
        int d   = idx >> 3;
        int qf4 = idx & 7;
        float4 v = *(const float4*)&Qt[(size_t)d * SS + qt * 32 + qf4 * 4];
        v.x *= 0.125f; v.y *= 0.125f; v.z *= 0.125f; v.w *= 0.125f;
        *(float4*)&As[d * 36 + qf4 * 4] = v;
    }

    // Preload K tile 0 via cp.async (8 float4 per thread).
    #pragma unroll
    for (int p = 0; p < 8; ++p) {
        int idx = p * 128 + tid;     // 0..1023 float4s
        int d   = idx >> 4;
        int kf4 = idx & 15;
        cpa16(&Bs[d * 68 + kf4 * 4], &Kt[(size_t)d * SS + kf4 * 4]);
    }
    cpa_commit();
    cpa_wait0();
    __syncthreads();                  // As + Bs(tile 0) ready

    // Hoist A fragments (loop-invariant across all k-tiles): 8 kc x 4 regs.
    float afr[8][4];
    #pragma unroll
    for (int kc = 0; kc < 8; ++kc) {
        const int d0 = kc * 8;
        afr[kc][0] = As[(d0 + tig)     * 36 + qb + g];
        afr[kc][1] = As[(d0 + tig)     * 36 + qb + g + 8];
        afr[kc][2] = As[(d0 + tig + 4) * 36 + qb + g];
        afr[kc][3] = As[(d0 + tig + 4) * 36 + qb + g + 8];
    }

    float tv[TOPK];
    int   ti[TOPK];
    #pragma unroll
    for (int t = 0; t < TOPK; ++t) { tv[t] = neg_inf(); ti[t] = 0x7FFFFFFF; }

    for (int kt = 0; kt < SS / 64; ++kt) {
        // Approx GEMM: 4 n-patches of m16n8, accumulated over 8 k-chunks.
        float c[4][4];
        #pragma unroll
        for (int p = 0; p < 4; ++p)
            #pragma unroll
            for (int j = 0; j < 4; ++j) c[p][j] = 0.f;

        #pragma unroll
        for (int kc = 0; kc < 8; ++kc) {
            const int d0 = kc * 8;
            #pragma unroll
            for (int p = 0; p < 4; ++p) {
                const int nb = kb + p * 8;
                float b0 = Bs[(d0 + tig)     * 68 + nb + g];
                float b1 = Bs[(d0 + tig + 4) * 68 + nb + g];
                asm volatile(
                    "mma.sync.aligned.m16n8k8.row.col.f32.tf32.tf32.f32 "
                    "{%0,%1,%2,%3}, {%4,%5,%6,%7}, {%8,%9}, {%0,%1,%2,%3};\n"
                    : "+f"(c[p][0]), "+f"(c[p][1]), "+f"(c[p][2]), "+f"(c[p][3])
                    : "r"(__float_as_uint(afr[kc][0])), "r"(__float_as_uint(afr[kc][1])),
                      "r"(__float_as_uint(afr[kc][2])), "r"(__float_as_uint(afr[kc][3])),
                      "r"(__float_as_uint(b0)), "r"(__float_as_uint(b1)));
            }
        }
        // Dump approx scores (C frag: c0/c1 at cols 2*tig,+1; c2/c3 at q+8).
        #pragma unroll
        for (int p = 0; p < 4; ++p) {
            const int col = kb + p * 8 + 2 * tig;
            *(float2*)&Sc[(qb + g)     * 68 + col] = make_float2(c[p][0], c[p][1]);
            *(float2*)&Sc[(qb + g + 8) * 68 + col] = make_float2(c[p][2], c[p][3]);
        }
        __syncthreads();             // Sc ready; all reads of Bs done

        // Prefetch next K tile into Bs — overlaps the scan below.
        if (kt + 1 < SS / 64) {
            #pragma unroll
            for (int p = 0; p < 8; ++p) {
                int idx = p * 128 + tid;
                int d   = idx >> 4;
                int kf4 = idx & 15;
                cpa16(&Bs[d * 68 + kf4 * 4],
                      &Kt[(size_t)d * SS + (kt + 1) * 64 + kf4 * 4]);
            }
            cpa_commit();
        }

        // Scan (approx values): per-thread top-10 with max-of-4 fast path.
        #pragma unroll
        for (int j4 = 0; j4 < 4; ++j4) {
            float4 s = *(const float4*)&Sc[srow * 68 + scg * 16 + j4 * 4];
            float mx4 = fmaxf(fmaxf(s.x, s.y), fmaxf(s.z, s.w));
            if (mx4 > tv[TOPK - 1]) {
                int k0 = kt * 64 + scg * 16 + j4 * 4;
                float sv[4] = {s.x, s.y, s.z, s.w};
                #pragma unroll
                for (int e = 0; e < 4; ++e) {
                    if (sv[e] > tv[TOPK - 1]) {
                        float vs = sv[e]; int is = k0 + e;
                        #pragma unroll
                        for (int t = 0; t < TOPK; ++t) {
                            if (vs > tv[t]) {
                                float tmpv = tv[t]; tv[t] = vs; vs = tmpv;
                                int tmpi = ti[t]; ti[t] = is; is = tmpi;
                            }
                        }
                    }
                }
            }
        }
        cpa_wait0();
        __syncthreads();             // next Bs tile resident; scans done
    }

    // Candidate INDICES into overlay (Bs dead after final sync above).
    #pragma unroll
    for (int t = 0; t < TOPK; ++t)
        ci[tid * TOPK + t] = ti[t];
    __syncthreads();

    // EXACT rescore of this thread's 10 candidates: serial ascending-d FMA
    // chain with the same As operands as the exact GEMM; K row from g_K.
    {
        const int r = tid >> 2;       // this thread's q row
        #pragma unroll
        for (int t = 0; t < TOPK; ++t) {
            int kidx = ci[tid * TOPK + t];
            const float4* krow = (const float4*)(Kr + (size_t)kidx * DH);
            float acc = 0.f;
            #pragma unroll
            for (int j = 0; j < 16; ++j) {
                float4 kv = krow[j];
                acc = fmaf(As[(j * 4 + 0) * 36 + r], kv.x, acc);
                acc = fmaf(As[(j * 4 + 1) * 36 + r], kv.y, acc);
                acc = fmaf(As[(j * 4 + 2) * 36 + r], kv.z, acc);
                acc = fmaf(As[(j * 4 + 3) * 36 + r], kv.w, acc);
            }
            cv[tid * TOPK + t] = acc;
        }
    }
    __syncthreads();

    // Merge 4 exact candidate lists per row; ties -> lower index (lax.top_k).
    if (tid < 32) {
        int base = tid * 4 * TOPK;
        for (int s = 0; s < TOPK; ++s) {
            float best = neg_inf(); int bi = 0x7FFFFFFF; int bp = 0;
            for (int p = 0; p < 4 * TOPK; ++p) {
                float v = cv[base + p]; int ii = ci[base + p];
                if (v > best || (v == best && ii < bi)) { best = v; bi = ii; bp = p; }
            }
            cv[base + bp] = neg_inf();
            pb[tid * TOPK + s] = best;
            tix[tid * TOPK + s] = bi;
        }
        float mx = pb[tid * TOPK];
        float pr[TOPK]; float Z = 0.f;
        #pragma unroll
        for (int s = 0; s < TOPK; ++s) {
            float e = expf(pb[tid * TOPK + s] - mx);
            pr[s] = e; Z += e;
        }
        #pragma unroll
        for (int s = 0; s < TOPK; ++s) pb[tid * TOPK + s] = pr[s] / Z;
    }
    __syncthreads();

    const int q = qt * 32 + srow;
    const size_t abase = ((size_t)bh * SS + q) * SS;
    for (int t = scg; t < TOPK; t += 4)
        out_attn[abase + tix[srow * TOPK + t]] = pb[srow * TOPK + t];

    // Context: 4 threads per row, 16 dh-columns each.
    float acc[16];
    #pragma unroll
    for (int j = 0; j < 16; ++j) acc[j] = 0.f;
    #pragma unroll
    for (int t = 0; t < TOPK; ++t) {
        float p = pb[srow * TOPK + t];
        const float* vr = &Vb[(size_t)tix[srow * TOPK + t] * DH + scg * 16];
        #pragma unroll
        for (int j4 = 0; j4 < 4; ++j4) {
            float4 v = *(const float4*)&vr[j4 * 4];
            acc[j4*4+0] = fmaf(p, v.x, acc[j4*4+0]);
            acc[j4*4+1] = fmaf(p, v.y, acc[j4*4+1]);
            acc[j4*4+2] = fmaf(p, v.z, acc[j4*4+2]);
            acc[j4*4+3] = fmaf(p, v.w, acc[j4*4+3]);
        }
    }
    const int b_ = bh >> 3, h_ = bh & 7;
    float* dst = out_ctx + ((size_t)(b_ * SS + q)) * DD + h_ * DH + scg * 16;
    #pragma unroll
    for (int j4 = 0; j4 < 4; ++j4) {
        float4 o;
        o.x = acc[j4*4+0]; o.y = acc[j4*4+1];
        o.z = acc[j4*4+2]; o.w = acc[j4*4+3];
        *(float4*)&dst[j4 * 4] = o;
    }
}

// ---------------------------------------------------------------------------
extern "C" void kernel_launch(void* const* d_in, const int* in_sizes, int n_in,
                              void* d_out, int out_size)
{
    const float* x  = (const float*)d_in[0];
    const float* Wq = (const float*)d_in[1];
    const float* bq = (const float*)d_in[2];
    const float* Wk = (const float*)d_in[3];
    const float* bk = (const float*)d_in[4];
    const float* Wv = (const float*)d_in[5];
    const float* bv = (const float*)d_in[6];

    float* out_ctx  = (float*)d_out;
    float* out_attn = out_ctx + (size_t)BB * SS * DD;

    // qkv also zero-fills out_attn (grid-stride, hidden in FMA shadow).
    dim3 g1(DD / 64, (BB * SS) / 64, 3);   // (8, 128, 3)
    qkv_kernel<<<g1, 256>>>(x, Wq, bq, Wk, bk, Wv, bv, out_attn);

    dim3 g2(SS / 32, BB * HH);             // (64, 32)
    attn_kernel<<<g2, 128>>>(out_ctx, out_attn);
}